// round 14
// baseline (speedup 1.0000x reference)
#include <cuda_runtime.h>
#include <cstdint>

#define HH 10
#define WW 10
#define TPB 64

__device__ double g_partials[8192];
__device__ unsigned int g_tick = 0;

__global__ __launch_bounds__(TPB) void loss_kernel(const float* __restrict__ res,
                                                   const int* __restrict__ pts,
                                                   int B, float* __restrict__ out) {
    __shared__ float s[TPB * 100];
    __shared__ float wsum[TPB / 32];
    __shared__ bool s_last;

    const int t = threadIdx.x;
    const int warp = t >> 5, lane = t & 31;
    const int blockSample = blockIdx.x * TPB;
    const int warpSample = blockSample + warp * 32;
    const int sample = blockSample + t;

    // load points early (latency hidden under staging)
    int4 p = make_int4(0, 0, 0, 0);
    if (sample < B) p = ((const int4*)pts)[sample];

    // ---- cooperative staging via cp.async: zero data registers, coalesced ----
    {
        int rem = B - warpSample;
        const float4* gsrc = (const float4*)(res + (size_t)warpSample * 100);
        unsigned sbase = (unsigned)__cvta_generic_to_shared(s + warp * 32 * 100);
        if (rem >= 32) {
#pragma unroll
            for (int i = 0; i < 25; i++) {
                asm volatile("cp.async.cg.shared.global [%0], [%1], 16;"
                             :: "r"(sbase + (unsigned)((i * 32 + lane) * 16)),
                                "l"(gsrc + i * 32 + lane));
            }
        } else if (rem > 0) {
            int n4 = rem * 25;
            for (int i = lane; i < n4; i += 32) {
                asm volatile("cp.async.cg.shared.global [%0], [%1], 16;"
                             :: "r"(sbase + (unsigned)(i * 16)),
                                "l"(gsrc + i));
            }
        }
        asm volatile("cp.async.commit_group;");
        asm volatile("cp.async.wait_group 0;");
    }
    __syncwarp();

    float loss = 0.0f;
    if (sample < B) {
        const float* r = s + t * 100;
        const float4* rp4 = (const float4*)r;
        const int p0y = p.x, p0x = p.y, p1y = p.z, p1x = p.w;
        const int ylo = min(p0y, p1y), yhi = max(p0y, p1y);
        const int xlo = min(p0x, p1x), xhi = max(p0x, p1x);
        const int ady = yhi - ylo, adx = xhi - xlo;
        const int base = ady + adx;
        const unsigned xmask = ((2u << xhi) - 1u) & ~((1u << xlo) - 1u);

        // ---- pass 1, grouped (2 rows per iter, unroll 1 -> low register peak):
        //      colsum[x] (all rows), colsumY[x] (rows inside y-interval, predicate
        //      hoisted per ROW instead of per-cell xmask test), row sums, lit bits ----
        float colsum[WW], colsumY[WW];
#pragma unroll
        for (int i = 0; i < WW; i++) { colsum[i] = 0.0f; colsumY[i] = 0.0f; }
        float det = 0.0f;
        unsigned long long m0 = 0ull, m1 = 0ull;
#pragma unroll 1
        for (int g = 0; g < 5; g++) {
            const float4* gp = (const float4*)(r + 20 * g);   // 80g bytes, 16-aligned
            float4 q[5];
#pragma unroll
            for (int i = 0; i < 5; i++) q[i] = gp[i];
            const bool inR0 = (unsigned)(2 * g - ylo) <= (unsigned)ady;
            const bool inR1 = (unsigned)(2 * g + 1 - ylo) <= (unsigned)ady;
            unsigned rm0 = 0u, rm1 = 0u;       // 10-bit lit masks, rows y0, y0+1
            float ra0 = 0.f, ra1 = 0.f;        // row sums
#pragma unroll
            for (int i = 0; i < 5; i++) {
                float vv[4] = {q[i].x, q[i].y, q[i].z, q[i].w};
#pragma unroll
                for (int k = 0; k < 4; k++) {
                    const int f = i * 4 + k;       // 0..19 compile-time
                    const int x = f % 10;          // compile-time
                    const float val = vv[k];
                    colsum[x] += val;
                    if (f < 10) {
                        ra0 += val;
                        if (inR0) colsumY[x] += val;
                        if (val > 0.5f) rm0 |= 1u << x;   // rint(val)==1 for [0,1)
                    } else {
                        ra1 += val;
                        if (inR1) colsumY[x] += val;
                        if (val > 0.5f) rm1 |= 1u << x;
                    }
                }
            }
            const int y0 = 2 * g, y1 = y0 + 1;
            const int d0 = max(0, max(ylo - y0, y0 - yhi));
            const int d1 = max(0, max(ylo - y1, y1 - yhi));
            det = fmaf((float)d0, ra0, det);
            det = fmaf((float)d1, ra1, det);
            const unsigned long long pairbits = (unsigned long long)rm0 |
                                                ((unsigned long long)rm1 << 12);
            if (y0 < 4)      m0 |= pairbits << (24 * g);
            else if (y0 == 4) { m0 |= (unsigned long long)rm0 << 48; m1 |= rm1; }
            else              m1 |= pairbits << (24 * g - 60);
        }
        float S = 0.0f, Srect = 0.0f;
#pragma unroll
        for (int x = 0; x < WW; x++) {
            S += colsum[x];
            const int dxf = max(0, max(xlo - x, x - xhi));
            det = fmaf((float)dxf, colsum[x], det);
            if (xmask & (1u << x)) Srect += colsumY[x];   // 10 predicated adds
        }
        const float rectCount = (float)((ady + 1) * (adx + 1));
        const float sc = fmaf(20.0f, rectCount - Srect, det);

        // ---- bit-parallel 8-connected flood fill from p0:
        //      2 dilations per exit check, 10 pairs == reference's 20 iters.
        //      No COLM masking needed: guard-bit bleed is scrubbed by &m. ----
        unsigned long long c0 = 0ull, c1 = 0ull;
        if (p0y < 5) c0 = 1ull << (p0y * 12 + p0x);
        else         c1 = 1ull << ((p0y - 5) * 12 + p0x);
#pragma unroll 1
        for (int it = 0; it < 10; it++) {
            unsigned long long s0 = c0 | (c0 << 1) | (c0 >> 1);
            unsigned long long s1 = c1 | (c1 << 1) | (c1 >> 1);
            unsigned long long n0 = c0 | ((s0 | (s0 << 12) | (s0 >> 12) | (s1 << 48)) & m0);
            unsigned long long n1 = c1 | ((s1 | (s1 << 12) | (s1 >> 12) | (s0 >> 48)) & m1);
            s0 = n0 | (n0 << 1) | (n0 >> 1);
            s1 = n1 | (n1 << 1) | (n1 >> 1);
            n0 |= (s0 | (s0 << 12) | (s0 >> 12) | (s1 << 48)) & m0;
            n1 |= (s1 | (s1 << 12) | (s1 >> 12) | (s0 >> 48)) & m1;
            const bool done = (n0 == c0) && (n1 == c1);
            c0 = n0; c1 = n1;
            if (done) break;
        }
        const int csize = __popcll(c0) + __popcll(c1);

        // per-row cluster bits
        unsigned cl[HH];
#pragma unroll
        for (int y = 0; y < 10; y++)
            cl[y] = (unsigned)((y < 5 ? (c0 >> (12 * y)) : (c1 >> (12 * (y - 5)))) & 0x3FFu);

        // ---- pass 2: S_cl, 4-way accumulators (chain 100 -> 25) ----
        float Scl0 = 0.f, Scl1 = 0.f, Scl2 = 0.f, Scl3 = 0.f;
#pragma unroll
        for (int c4 = 0; c4 < 25; c4++) {
            float4 v = rp4[c4];
            float vv[4] = {v.x, v.y, v.z, v.w};
#pragma unroll
            for (int k = 0; k < 4; k++) {
                const int f = c4 * 4 + k;
                const int y = f / 10, x = f % 10;
                if (cl[x] & (1u << y)) {
                    if (k == 0) Scl0 += vv[k];
                    else if (k == 1) Scl1 += vv[k];
                    else if (k == 2) Scl2 += vv[k];
                    else Scl3 += vv[k];
                }
            }
        }
        const float Scl = (Scl0 + Scl1) + (Scl2 + Scl3);

        // ---- branch-free argmin over cluster of dist-to-end
        //      (ties: smaller y first; left candidate, tried first with <=,
        //       matches jnp.argmin first-flat-index exactly) ----
        int minv = HH * WW + 10, bny = p0y, bnx = p0x;
#pragma unroll
        for (int y = 0; y < 10; y++) {
            const unsigned bits = cl[y];
            const int dy = abs(y - p1y);
            const unsigned left = bits & ((2u << p1x) - 1u);
            const unsigned right = bits >> p1x;
            const int xl = 31 - __clz(left);                 // -1 if none
            const int dl = left ? (dy + p1x - xl) : 999;
            const int dr = right ? (dy + (__ffs(right) - 1)) : 999;
            const bool takeL = dl <= dr;
            const int d = takeL ? dl : dr;
            const int xc = takeL ? xl : (p1x + __ffs(right) - 1);
            if (d < minv) { minv = d; bny = y; bnx = xc; }
        }
        const bool better = minv < base;
        const int ny = better ? bny : p0y;
        const int nx = better ? bnx : p0x;
        const int gap = min(base, minv);

        // ---- neighbor-toward-end cascade ----
        int by = ny, bx = nx, bg = gap;
        const int oy = p1y - ny, ox = p1x - nx;
#define UPD(cond, cy, cx) do { \
            const int _cy = (cy), _cx = (cx); \
            const int _d = abs(_cy - p1y) + abs(_cx - p1x); \
            if ((cond) && _d < bg) { by = _cy; bx = _cx; bg = _d; } \
        } while (0)
        UPD(ox < 0, ny, nx - 1);
        UPD(ox < 0 && ny != 0, ny - 1, nx - 1);
        UPD(ox < 0 && ny != HH - 1, ny + 1, nx - 1);
        UPD(ox > 0, ny, nx + 1);
        UPD(ox > 0 && ny != 0, ny - 1, nx + 1);
        UPD(ox > 0 && ny != HH - 1, ny + 1, nx + 1);
        UPD(oy < 0, ny - 1, nx);
        UPD(oy > 0, ny + 1, nx);
#undef UPD
        const int ncy = min(max(by, 0), HH - 1);
        const int ncx = min(max(bx, 0), WW - 1);

        // ---- assemble (scalar lookups from smem) ----
        const float r0 = r[p0y * 10 + p0x];
        const float r1 = r[p1y * 10 + p1x];
        const float csz = (float)csize;
        const float loss_start = (2.0f - (r0 + r1)) * 1000.0f;
        const float lonely = 15.0f * S + 5.0f * csz - 20.0f * Scl;
        const float cpen = 12.0f * csz * Scl;
        const float gpen = (float)gap * 300.0f * (1.0f - r[ncy * 10 + ncx]);
        loss = loss_start + lonely + sc + cpen + gpen;
    }

    // ---- block reduction -> double partial ----
    float l = loss;
#pragma unroll
    for (int o = 16; o; o >>= 1) l += __shfl_xor_sync(0xFFFFFFFFu, l, o);
    if (lane == 0) wsum[warp] = l;
    __syncthreads();
    if (t == 0) {
        double acc = 0.0;
#pragma unroll
        for (int w = 0; w < TPB / 32; w++) acc += (double)wsum[w];
        g_partials[blockIdx.x] = acc;
        __threadfence();
        unsigned int ticket = atomicAdd(&g_tick, 1u);
        s_last = (ticket == gridDim.x - 1);
    }
    __syncthreads();

    // ---- last block: deterministic final sum, write out, reset counter ----
    if (s_last) {
        const int n = gridDim.x;
        double a0 = 0.0, a1 = 0.0, a2 = 0.0, a3 = 0.0;
        for (int i = t; i + 3 * TPB < n; i += 4 * TPB) {
            a0 += g_partials[i];
            a1 += g_partials[i + TPB];
            a2 += g_partials[i + 2 * TPB];
            a3 += g_partials[i + 3 * TPB];
        }
        {
            int i = t + ((n / (4 * TPB)) * 4 * TPB);
            for (; i < n; i += TPB) a0 += g_partials[i];
        }
        double a = (a0 + a1) + (a2 + a3);
#pragma unroll
        for (int o = 16; o; o >>= 1) a += __shfl_xor_sync(0xFFFFFFFFu, a, o);
        __shared__ double dsum[TPB / 32];
        if (lane == 0) dsum[warp] = a;
        __syncthreads();
        if (t == 0) {
            double tot = 0.0;
#pragma unroll
            for (int w = 0; w < TPB / 32; w++) tot += dsum[w];
            out[0] = (float)tot;
            __threadfence();
            g_tick = 0;   // reset for next graph replay
        }
    }
}

extern "C" void kernel_launch(void* const* d_in, const int* in_sizes, int n_in,
                              void* d_out, int out_size) {
    const float* res = (const float*)d_in[0];
    const int* pts = (const int*)d_in[1];
    const int B = in_sizes[0] / 100;
    const int nblk = (B + TPB - 1) / TPB;   // 4096 for B=262144
    loss_kernel<<<nblk, TPB>>>(res, pts, B, (float*)d_out);
}

// round 15
// speedup vs baseline: 1.4638x; 1.4638x over previous
#include <cuda_runtime.h>
#include <cstdint>

#define HH 10
#define WW 10
#define TPB 64

__device__ double g_partials[8192];
__device__ unsigned int g_tick = 0;

__global__ __launch_bounds__(TPB) void loss_kernel(const float* __restrict__ res,
                                                   const int* __restrict__ pts,
                                                   int B, float* __restrict__ out) {
    __shared__ float s[TPB * 100];
    __shared__ float wsum[TPB / 32];
    __shared__ bool s_last;

    const int t = threadIdx.x;
    const int warp = t >> 5, lane = t & 31;
    const int blockSample = blockIdx.x * TPB;
    const int warpSample = blockSample + warp * 32;
    const int sample = blockSample + t;

    // load points early (latency hidden under staging)
    int4 p = make_int4(0, 0, 0, 0);
    if (sample < B) p = ((const int4*)pts)[sample];

    // ---- cooperative staging via cp.async: zero data registers, coalesced ----
    {
        int rem = B - warpSample;
        const float4* gsrc = (const float4*)(res + (size_t)warpSample * 100);
        unsigned sbase = (unsigned)__cvta_generic_to_shared(s + warp * 32 * 100);
        if (rem >= 32) {
#pragma unroll
            for (int i = 0; i < 25; i++) {
                asm volatile("cp.async.cg.shared.global [%0], [%1], 16;"
                             :: "r"(sbase + (unsigned)((i * 32 + lane) * 16)),
                                "l"(gsrc + i * 32 + lane));
            }
        } else if (rem > 0) {
            int n4 = rem * 25;
            for (int i = lane; i < n4; i += 32) {
                asm volatile("cp.async.cg.shared.global [%0], [%1], 16;"
                             :: "r"(sbase + (unsigned)(i * 16)),
                                "l"(gsrc + i));
            }
        }
        asm volatile("cp.async.commit_group;");
        asm volatile("cp.async.wait_group 0;");
    }
    __syncwarp();

    float loss = 0.0f;
    if (sample < B) {
        const float* r = s + t * 100;
        const float4* rp4 = (const float4*)r;
        const int p0y = p.x, p0x = p.y, p1y = p.z, p1x = p.w;
        const int ylo = min(p0y, p1y), yhi = max(p0y, p1y);
        const int xlo = min(p0x, p1x), xhi = max(p0x, p1x);
        const int ady = yhi - ylo, adx = xhi - xlo;
        const int base = ady + adx;
        const unsigned xmask = ((2u << xhi) - 1u) & ~((1u << xlo) - 1u);

        // 0/1 float column weights for the rect sum (10 SELs, once)
        float wx[WW];
#pragma unroll
        for (int i = 0; i < WW; i++) wx[i] = ((xmask >> i) & 1u) ? 1.0f : 0.0f;

        // ---- pass 1, grouped (2 rows per iter, unroll 1 -> low register peak) ----
        float colsum[WW];
#pragma unroll
        for (int i = 0; i < WW; i++) colsum[i] = 0.0f;
        float Srect = 0.0f, det = 0.0f;
        unsigned long long m0 = 0ull, m1 = 0ull;
#pragma unroll 1
        for (int g = 0; g < 5; g++) {
            const float4* gp = (const float4*)(r + 20 * g);   // 80g bytes, 16-aligned
            float4 q[5];
#pragma unroll
            for (int i = 0; i < 5; i++) q[i] = gp[i];
            unsigned rm0 = 0u, rm1 = 0u;       // 10-bit lit masks, rows y0, y0+1
            float ra0 = 0.f, ra1 = 0.f;        // row sums
            float rr0 = 0.f, rr1 = 0.f;        // rect-masked row sums (FFMA w/ 0/1 wt)
#pragma unroll
            for (int i = 0; i < 5; i++) {
                float vv[4] = {q[i].x, q[i].y, q[i].z, q[i].w};
#pragma unroll
                for (int k = 0; k < 4; k++) {
                    const int f = i * 4 + k;       // 0..19 compile-time
                    const int x = f % 10;          // compile-time
                    const float val = vv[k];
                    colsum[x] += val;
                    if (f < 10) {
                        ra0 += val;
                        rr0 = fmaf(val, wx[x], rr0);           // exact: val*1 or +0
                        if (val > 0.5f) rm0 |= 1u << x;        // rint(val)==1 on [0,1)
                    } else {
                        ra1 += val;
                        rr1 = fmaf(val, wx[x], rr1);
                        if (val > 0.5f) rm1 |= 1u << x;
                    }
                }
            }
            const int y0 = 2 * g, y1 = y0 + 1;
            const int d0 = max(0, max(ylo - y0, y0 - yhi));
            const int d1 = max(0, max(ylo - y1, y1 - yhi));
            det = fmaf((float)d0, ra0, det);
            det = fmaf((float)d1, ra1, det);
            if ((unsigned)(y0 - ylo) <= (unsigned)ady) Srect += rr0;
            if ((unsigned)(y1 - ylo) <= (unsigned)ady) Srect += rr1;
            const unsigned long long pairbits = (unsigned long long)rm0 |
                                                ((unsigned long long)rm1 << 12);
            if (y0 < 4)      m0 |= pairbits << (24 * g);
            else if (y0 == 4) { m0 |= (unsigned long long)rm0 << 48; m1 |= rm1; }
            else              m1 |= pairbits << (24 * g - 60);
        }
        float S = 0.0f;
#pragma unroll
        for (int x = 0; x < WW; x++) {
            S += colsum[x];
            const int dxf = max(0, max(xlo - x, x - xhi));
            det = fmaf((float)dxf, colsum[x], det);
        }
        const float rectCount = (float)((ady + 1) * (adx + 1));
        const float sc = fmaf(20.0f, rectCount - Srect, det);

        // ---- bit-parallel 8-connected flood fill from p0:
        //      2 dilations per exit check, 10 pairs == reference's 20 iters.
        //      No COLM masking needed: guard-bit bleed is scrubbed by &m. ----
        unsigned long long c0 = 0ull, c1 = 0ull;
        if (p0y < 5) c0 = 1ull << (p0y * 12 + p0x);
        else         c1 = 1ull << ((p0y - 5) * 12 + p0x);
#pragma unroll 1
        for (int it = 0; it < 10; it++) {
            unsigned long long s0 = c0 | (c0 << 1) | (c0 >> 1);
            unsigned long long s1 = c1 | (c1 << 1) | (c1 >> 1);
            unsigned long long n0 = c0 | ((s0 | (s0 << 12) | (s0 >> 12) | (s1 << 48)) & m0);
            unsigned long long n1 = c1 | ((s1 | (s1 << 12) | (s1 >> 12) | (s0 >> 48)) & m1);
            s0 = n0 | (n0 << 1) | (n0 >> 1);
            s1 = n1 | (n1 << 1) | (n1 >> 1);
            n0 |= (s0 | (s0 << 12) | (s0 >> 12) | (s1 << 48)) & m0;
            n1 |= (s1 | (s1 << 12) | (s1 >> 12) | (s0 >> 48)) & m1;
            const bool done = (n0 == c0) && (n1 == c1);
            c0 = n0; c1 = n1;
            if (done) break;
        }
        const int csize = __popcll(c0) + __popcll(c1);

        // per-row cluster bits
        unsigned cl[HH];
#pragma unroll
        for (int y = 0; y < 10; y++)
            cl[y] = (unsigned)((y < 5 ? (c0 >> (12 * y)) : (c1 >> (12 * (y - 5)))) & 0x3FFu);

        // ---- pass 2: S_cl, 4-way accumulators (chain 100 -> 25) ----
        float Scl0 = 0.f, Scl1 = 0.f, Scl2 = 0.f, Scl3 = 0.f;
#pragma unroll
        for (int c4 = 0; c4 < 25; c4++) {
            float4 v = rp4[c4];
            float vv[4] = {v.x, v.y, v.z, v.w};
#pragma unroll
            for (int k = 0; k < 4; k++) {
                const int f = c4 * 4 + k;
                const int y = f / 10, x = f % 10;
                if (cl[x] & (1u << y)) {
                    if (k == 0) Scl0 += vv[k];
                    else if (k == 1) Scl1 += vv[k];
                    else if (k == 2) Scl2 += vv[k];
                    else Scl3 += vv[k];
                }
            }
        }
        const float Scl = (Scl0 + Scl1) + (Scl2 + Scl3);

        // ---- branch-free argmin over cluster of dist-to-end
        //      (ties: smaller y first; left candidate, tried first with <=,
        //       matches jnp.argmin first-flat-index exactly) ----
        int minv = HH * WW + 10, bny = p0y, bnx = p0x;
#pragma unroll
        for (int y = 0; y < 10; y++) {
            const unsigned bits = cl[y];
            const int dy = abs(y - p1y);
            const unsigned left = bits & ((2u << p1x) - 1u);
            const unsigned right = bits >> p1x;
            const int xl = 31 - __clz(left);                 // -1 if none
            const int dl = left ? (dy + p1x - xl) : 999;
            const int dr = right ? (dy + (__ffs(right) - 1)) : 999;
            const bool takeL = dl <= dr;
            const int d = takeL ? dl : dr;
            const int xc = takeL ? xl : (p1x + __ffs(right) - 1);
            if (d < minv) { minv = d; bny = y; bnx = xc; }
        }
        const bool better = minv < base;
        const int ny = better ? bny : p0y;
        const int nx = better ? bnx : p0x;
        const int gap = min(base, minv);

        // ---- neighbor-toward-end cascade ----
        int by = ny, bx = nx, bg = gap;
        const int oy = p1y - ny, ox = p1x - nx;
#define UPD(cond, cy, cx) do { \
            const int _cy = (cy), _cx = (cx); \
            const int _d = abs(_cy - p1y) + abs(_cx - p1x); \
            if ((cond) && _d < bg) { by = _cy; bx = _cx; bg = _d; } \
        } while (0)
        UPD(ox < 0, ny, nx - 1);
        UPD(ox < 0 && ny != 0, ny - 1, nx - 1);
        UPD(ox < 0 && ny != HH - 1, ny + 1, nx - 1);
        UPD(ox > 0, ny, nx + 1);
        UPD(ox > 0 && ny != 0, ny - 1, nx + 1);
        UPD(ox > 0 && ny != HH - 1, ny + 1, nx + 1);
        UPD(oy < 0, ny - 1, nx);
        UPD(oy > 0, ny + 1, nx);
#undef UPD
        const int ncy = min(max(by, 0), HH - 1);
        const int ncx = min(max(bx, 0), WW - 1);

        // ---- assemble (scalar lookups from smem) ----
        const float r0 = r[p0y * 10 + p0x];
        const float r1 = r[p1y * 10 + p1x];
        const float csz = (float)csize;
        const float loss_start = (2.0f - (r0 + r1)) * 1000.0f;
        const float lonely = 15.0f * S + 5.0f * csz - 20.0f * Scl;
        const float cpen = 12.0f * csz * Scl;
        const float gpen = (float)gap * 300.0f * (1.0f - r[ncy * 10 + ncx]);
        loss = loss_start + lonely + sc + cpen + gpen;
    }

    // ---- block reduction -> double partial ----
    float l = loss;
#pragma unroll
    for (int o = 16; o; o >>= 1) l += __shfl_xor_sync(0xFFFFFFFFu, l, o);
    if (lane == 0) wsum[warp] = l;
    __syncthreads();
    if (t == 0) {
        double acc = 0.0;
#pragma unroll
        for (int w = 0; w < TPB / 32; w++) acc += (double)wsum[w];
        g_partials[blockIdx.x] = acc;
        __threadfence();
        unsigned int ticket = atomicAdd(&g_tick, 1u);
        s_last = (ticket == gridDim.x - 1);
    }
    __syncthreads();

    // ---- last block: deterministic final sum, write out, reset counter ----
    if (s_last) {
        const int n = gridDim.x;
        double a0 = 0.0, a1 = 0.0, a2 = 0.0, a3 = 0.0;
        for (int i = t; i + 3 * TPB < n; i += 4 * TPB) {
            a0 += g_partials[i];
            a1 += g_partials[i + TPB];
            a2 += g_partials[i + 2 * TPB];
            a3 += g_partials[i + 3 * TPB];
        }
        {
            int i = t + ((n / (4 * TPB)) * 4 * TPB);
            for (; i < n; i += TPB) a0 += g_partials[i];
        }
        double a = (a0 + a1) + (a2 + a3);
#pragma unroll
        for (int o = 16; o; o >>= 1) a += __shfl_xor_sync(0xFFFFFFFFu, a, o);
        __shared__ double dsum[TPB / 32];
        if (lane == 0) dsum[warp] = a;
        __syncthreads();
        if (t == 0) {
            double tot = 0.0;
#pragma unroll
            for (int w = 0; w < TPB / 32; w++) tot += dsum[w];
            out[0] = (float)tot;
            __threadfence();
            g_tick = 0;   // reset for next graph replay
        }
    }
}

extern "C" void kernel_launch(void* const* d_in, const int* in_sizes, int n_in,
                              void* d_out, int out_size) {
    const float* res = (const float*)d_in[0];
    const int* pts = (const int*)d_in[1];
    const int B = in_sizes[0] / 100;
    const int nblk = (B + TPB - 1) / TPB;   // 4096 for B=262144
    loss_kernel<<<nblk, TPB>>>(res, pts, B, (float*)d_out);
}

// round 16
// speedup vs baseline: 1.4651x; 1.0009x over previous
#include <cuda_runtime.h>
#include <cstdint>

#define HH 10
#define WW 10
#define TPB 64

__device__ double g_partials[8192];
__device__ unsigned int g_tick = 0;

__global__ __launch_bounds__(TPB) void loss_kernel(const float* __restrict__ res,
                                                   const int* __restrict__ pts,
                                                   int B, float* __restrict__ out) {
    __shared__ float s[TPB * 100];
    __shared__ float wsum[TPB / 32];
    __shared__ bool s_last;

    const int t = threadIdx.x;
    const int warp = t >> 5, lane = t & 31;
    const int blockSample = blockIdx.x * TPB;
    const int warpSample = blockSample + warp * 32;
    const int sample = blockSample + t;

    // load points early (latency hidden under staging)
    int4 p = make_int4(0, 0, 0, 0);
    if (sample < B) p = ((const int4*)pts)[sample];

    // ---- cooperative staging via cp.async: zero data registers, coalesced ----
    {
        int rem = B - warpSample;
        const float4* gsrc = (const float4*)(res + (size_t)warpSample * 100);
        unsigned sbase = (unsigned)__cvta_generic_to_shared(s + warp * 32 * 100);
        if (rem >= 32) {
#pragma unroll
            for (int i = 0; i < 25; i++) {
                asm volatile("cp.async.cg.shared.global [%0], [%1], 16;"
                             :: "r"(sbase + (unsigned)((i * 32 + lane) * 16)),
                                "l"(gsrc + i * 32 + lane));
            }
        } else if (rem > 0) {
            int n4 = rem * 25;
            for (int i = lane; i < n4; i += 32) {
                asm volatile("cp.async.cg.shared.global [%0], [%1], 16;"
                             :: "r"(sbase + (unsigned)(i * 16)),
                                "l"(gsrc + i));
            }
        }
        asm volatile("cp.async.commit_group;");
        asm volatile("cp.async.wait_group 0;");
    }
    __syncwarp();

    float loss = 0.0f;
    if (sample < B) {
        const float* r = s + t * 100;
        const float4* rp4 = (const float4*)r;
        const int p0y = p.x, p0x = p.y, p1y = p.z, p1x = p.w;
        const int ylo = min(p0y, p1y), yhi = max(p0y, p1y);
        const int xlo = min(p0x, p1x), xhi = max(p0x, p1x);
        const int ady = yhi - ylo, adx = xhi - xlo;
        const int base = ady + adx;
        const unsigned xmask = ((2u << xhi) - 1u) & ~((1u << xlo) - 1u);

        // per-column float tables built once:
        //   wx[x]  = 1 if x inside [xlo,xhi] else 0   (rect weight)
        //   dxw[x] = distance of x to [xlo,xhi]       (x-detour weight)
        float wx[WW], dxw[WW];
#pragma unroll
        for (int i = 0; i < WW; i++) {
            wx[i] = ((xmask >> i) & 1u) ? 1.0f : 0.0f;
            dxw[i] = (float)max(0, max(xlo - i, i - xhi));
        }

        // ---- pass 1, grouped (2 rows per iter, unroll 1 -> low register peak) ----
        float S = 0.0f, Srect = 0.0f, det0 = 0.0f, det1 = 0.0f;
        unsigned long long m0 = 0ull, m1 = 0ull;
#pragma unroll 1
        for (int g = 0; g < 5; g++) {
            const float4* gp = (const float4*)(r + 20 * g);   // 80g bytes, 16-aligned
            float4 q[5];
#pragma unroll
            for (int i = 0; i < 5; i++) q[i] = gp[i];
            unsigned rm0 = 0u, rm1 = 0u;       // 10-bit lit masks, rows y0, y0+1
            float ra0 = 0.f, ra1 = 0.f;        // row sums
            float rr0 = 0.f, rr1 = 0.f;        // rect-masked row sums (FFMA w/ 0/1 wt)
#pragma unroll
            for (int i = 0; i < 5; i++) {
                float vv[4] = {q[i].x, q[i].y, q[i].z, q[i].w};
#pragma unroll
                for (int k = 0; k < 4; k++) {
                    const int f = i * 4 + k;       // 0..19 compile-time
                    const int x = f % 10;          // compile-time
                    const float val = vv[k];
                    if (f < 10) {
                        ra0 += val;
                        rr0 = fmaf(val, wx[x], rr0);           // exact: val*1 or +0
                        det0 = fmaf(val, dxw[x], det0);        // x-detour contribution
                        if (val > 0.5f) rm0 |= 1u << x;        // rint(val)==1 on [0,1)
                    } else {
                        ra1 += val;
                        rr1 = fmaf(val, wx[x], rr1);
                        det1 = fmaf(val, dxw[x], det1);
                        if (val > 0.5f) rm1 |= 1u << x;
                    }
                }
            }
            const int y0 = 2 * g, y1 = y0 + 1;
            const int d0 = max(0, max(ylo - y0, y0 - yhi));
            const int d1 = max(0, max(ylo - y1, y1 - yhi));
            det0 = fmaf((float)d0, ra0, det0);                 // y-detour contribution
            det1 = fmaf((float)d1, ra1, det1);
            S += ra0 + ra1;
            if ((unsigned)(y0 - ylo) <= (unsigned)ady) Srect += rr0;
            if ((unsigned)(y1 - ylo) <= (unsigned)ady) Srect += rr1;
            const unsigned long long pairbits = (unsigned long long)rm0 |
                                                ((unsigned long long)rm1 << 12);
            if (y0 < 4)      m0 |= pairbits << (24 * g);
            else if (y0 == 4) { m0 |= (unsigned long long)rm0 << 48; m1 |= rm1; }
            else              m1 |= pairbits << (24 * g - 60);
        }
        const float det = det0 + det1;
        const float rectCount = (float)((ady + 1) * (adx + 1));
        const float sc = fmaf(20.0f, rectCount - Srect, det);

        // ---- bit-parallel 8-connected flood fill from p0:
        //      2 dilations per exit check, 10 pairs == reference's 20 iters.
        //      No COLM masking needed: guard-bit bleed is scrubbed by &m. ----
        unsigned long long c0 = 0ull, c1 = 0ull;
        if (p0y < 5) c0 = 1ull << (p0y * 12 + p0x);
        else         c1 = 1ull << ((p0y - 5) * 12 + p0x);
#pragma unroll 1
        for (int it = 0; it < 10; it++) {
            unsigned long long s0 = c0 | (c0 << 1) | (c0 >> 1);
            unsigned long long s1 = c1 | (c1 << 1) | (c1 >> 1);
            unsigned long long n0 = c0 | ((s0 | (s0 << 12) | (s0 >> 12) | (s1 << 48)) & m0);
            unsigned long long n1 = c1 | ((s1 | (s1 << 12) | (s1 >> 12) | (s0 >> 48)) & m1);
            s0 = n0 | (n0 << 1) | (n0 >> 1);
            s1 = n1 | (n1 << 1) | (n1 >> 1);
            n0 |= (s0 | (s0 << 12) | (s0 >> 12) | (s1 << 48)) & m0;
            n1 |= (s1 | (s1 << 12) | (s1 >> 12) | (s0 >> 48)) & m1;
            const bool done = (n0 == c0) && (n1 == c1);
            c0 = n0; c1 = n1;
            if (done) break;
        }
        const int csize = __popcll(c0) + __popcll(c1);

        // per-row cluster bits
        unsigned cl[HH];
#pragma unroll
        for (int y = 0; y < 10; y++)
            cl[y] = (unsigned)((y < 5 ? (c0 >> (12 * y)) : (c1 >> (12 * (y - 5)))) & 0x3FFu);

        // ---- pass 2: S_cl, 4-way accumulators (chain 100 -> 25) ----
        float Scl0 = 0.f, Scl1 = 0.f, Scl2 = 0.f, Scl3 = 0.f;
#pragma unroll
        for (int c4 = 0; c4 < 25; c4++) {
            float4 v = rp4[c4];
            float vv[4] = {v.x, v.y, v.z, v.w};
#pragma unroll
            for (int k = 0; k < 4; k++) {
                const int f = c4 * 4 + k;
                const int y = f / 10, x = f % 10;
                if (cl[x] & (1u << y)) {
                    if (k == 0) Scl0 += vv[k];
                    else if (k == 1) Scl1 += vv[k];
                    else if (k == 2) Scl2 += vv[k];
                    else Scl3 += vv[k];
                }
            }
        }
        const float Scl = (Scl0 + Scl1) + (Scl2 + Scl3);

        // ---- branch-free argmin over cluster of dist-to-end
        //      (ties: smaller y first; left candidate, tried first with <=,
        //       matches jnp.argmin first-flat-index exactly) ----
        int minv = HH * WW + 10, bny = p0y, bnx = p0x;
#pragma unroll
        for (int y = 0; y < 10; y++) {
            const unsigned bits = cl[y];
            const int dy = abs(y - p1y);
            const unsigned left = bits & ((2u << p1x) - 1u);
            const unsigned right = bits >> p1x;
            const int xl = 31 - __clz(left);                 // -1 if none
            const int dl = left ? (dy + p1x - xl) : 999;
            const int dr = right ? (dy + (__ffs(right) - 1)) : 999;
            const bool takeL = dl <= dr;
            const int d = takeL ? dl : dr;
            const int xc = takeL ? xl : (p1x + __ffs(right) - 1);
            if (d < minv) { minv = d; bny = y; bnx = xc; }
        }
        const bool better = minv < base;
        const int ny = better ? bny : p0y;
        const int nx = better ? bnx : p0x;
        const int gap = min(base, minv);

        // ---- neighbor-toward-end cascade ----
        int by = ny, bx = nx, bg = gap;
        const int oy = p1y - ny, ox = p1x - nx;
#define UPD(cond, cy, cx) do { \
            const int _cy = (cy), _cx = (cx); \
            const int _d = abs(_cy - p1y) + abs(_cx - p1x); \
            if ((cond) && _d < bg) { by = _cy; bx = _cx; bg = _d; } \
        } while (0)
        UPD(ox < 0, ny, nx - 1);
        UPD(ox < 0 && ny != 0, ny - 1, nx - 1);
        UPD(ox < 0 && ny != HH - 1, ny + 1, nx - 1);
        UPD(ox > 0, ny, nx + 1);
        UPD(ox > 0 && ny != 0, ny - 1, nx + 1);
        UPD(ox > 0 && ny != HH - 1, ny + 1, nx + 1);
        UPD(oy < 0, ny - 1, nx);
        UPD(oy > 0, ny + 1, nx);
#undef UPD
        const int ncy = min(max(by, 0), HH - 1);
        const int ncx = min(max(bx, 0), WW - 1);

        // ---- assemble (scalar lookups from smem) ----
        const float r0 = r[p0y * 10 + p0x];
        const float r1 = r[p1y * 10 + p1x];
        const float csz = (float)csize;
        const float loss_start = (2.0f - (r0 + r1)) * 1000.0f;
        const float lonely = 15.0f * S + 5.0f * csz - 20.0f * Scl;
        const float cpen = 12.0f * csz * Scl;
        const float gpen = (float)gap * 300.0f * (1.0f - r[ncy * 10 + ncx]);
        loss = loss_start + lonely + sc + cpen + gpen;
    }

    // ---- block reduction -> double partial ----
    float l = loss;
#pragma unroll
    for (int o = 16; o; o >>= 1) l += __shfl_xor_sync(0xFFFFFFFFu, l, o);
    if (lane == 0) wsum[warp] = l;
    __syncthreads();
    if (t == 0) {
        double acc = 0.0;
#pragma unroll
        for (int w = 0; w < TPB / 32; w++) acc += (double)wsum[w];
        g_partials[blockIdx.x] = acc;
        __threadfence();
        unsigned int ticket = atomicAdd(&g_tick, 1u);
        s_last = (ticket == gridDim.x - 1);
    }
    __syncthreads();

    // ---- last block: deterministic final sum (double2 loads, 8-deep MLP) ----
    if (s_last) {
        const int n = gridDim.x;
        const int n2 = n >> 1;                       // double2 count
        const double2* gp2 = (const double2*)g_partials;
        double a0 = 0.0, a1 = 0.0, a2 = 0.0, a3 = 0.0;
        int i = t;
        for (; i + 3 * TPB < n2; i += 4 * TPB) {
            const double2 v0 = gp2[i];
            const double2 v1 = gp2[i + TPB];
            const double2 v2 = gp2[i + 2 * TPB];
            const double2 v3 = gp2[i + 3 * TPB];
            a0 += v0.x + v0.y;
            a1 += v1.x + v1.y;
            a2 += v2.x + v2.y;
            a3 += v3.x + v3.y;
        }
        for (; i < n2; i += TPB) { const double2 v = gp2[i]; a0 += v.x + v.y; }
        if ((n & 1) && t == 0) a0 += g_partials[n - 1];
        double a = (a0 + a1) + (a2 + a3);
#pragma unroll
        for (int o = 16; o; o >>= 1) a += __shfl_xor_sync(0xFFFFFFFFu, a, o);
        __shared__ double dsum[TPB / 32];
        if (lane == 0) dsum[warp] = a;
        __syncthreads();
        if (t == 0) {
            double tot = 0.0;
#pragma unroll
            for (int w = 0; w < TPB / 32; w++) tot += dsum[w];
            out[0] = (float)tot;
            __threadfence();
            g_tick = 0;   // reset for next graph replay
        }
    }
}

extern "C" void kernel_launch(void* const* d_in, const int* in_sizes, int n_in,
                              void* d_out, int out_size) {
    const float* res = (const float*)d_in[0];
    const int* pts = (const int*)d_in[1];
    const int B = in_sizes[0] / 100;
    const int nblk = (B + TPB - 1) / TPB;   // 4096 for B=262144
    loss_kernel<<<nblk, TPB>>>(res, pts, B, (float*)d_out);
}